// round 2
// baseline (speedup 1.0000x reference)
#include <cuda_runtime.h>
#include <cstdint>

#define B_   64
#define T_   1024
#define F_   256
#define U_   512
#define G_   1536             // 3*U
#define P_   1024             // 2*U
#define GB_  (G_*B_)          // 98304
#define HB_  (U_*B_)          // 32768 floats per h ping-pong buffer
#define EPS_ 1e-3f

// ---------------------------------------------------------------------------
// Scratch: __device__ globals (allocation-free per harness rules)
// ---------------------------------------------------------------------------
__device__ float g_xwf[(size_t)T_ * G_ * B_];   // [T][G][B]  x@Wf + bi_f
__device__ float g_xwb[(size_t)T_ * G_ * B_];   // [T][G][B]  x@Wb + bi_b
__device__ float g_resid[(size_t)B_ * T_ * P_]; // [B*T][P]   x@Wp
__device__ float g_hf[(size_t)B_ * T_ * U_];    // [B][T][U]
__device__ float g_hb[(size_t)B_ * T_ * U_];    // [B][T][U]
__device__ float g_hbuf[2 * 2 * HB_];           // [dir][parity][U][B]
__device__ unsigned g_barc[2];                  // barrier arrive counters
__device__ unsigned g_barg[2];                  // barrier generations

// ---------------------------------------------------------------------------
// f32x2 packed FMA (Blackwell dual-fp32; only reachable via PTX)
// ---------------------------------------------------------------------------
__device__ __forceinline__ void fma2(float2& d, float2 a, float2 b) {
    unsigned long long& dd = reinterpret_cast<unsigned long long&>(d);
    unsigned long long& aa = reinterpret_cast<unsigned long long&>(a);
    unsigned long long& bb = reinterpret_cast<unsigned long long&>(b);
    asm("fma.rn.f32x2 %0, %1, %2, %0;" : "+l"(dd) : "l"(aa), "l"(bb));
}
__device__ __forceinline__ float2 dup2(float x) { return make_float2(x, x); }

// ---------------------------------------------------------------------------
// Init: zero h0 buffers + barrier state (graph replays reuse globals)
// ---------------------------------------------------------------------------
__global__ void init_kernel() {
    int idx = blockIdx.x * blockDim.x + threadIdx.x;
    int stride = gridDim.x * blockDim.x;
    for (int i = idx; i < 2 * 2 * HB_; i += stride) g_hbuf[i] = 0.0f;
    if (idx < 2) { g_barc[idx] = 0u; g_barg[idx] = 0u; }
}

// ---------------------------------------------------------------------------
// fp32 GEMM: A[BT,256] x Bw[256,N].  64x64 tile, BK=16, 256 threads.
//  mode 0 -> g_xwf [t][g][b] (+bias), mode 1 -> g_xwb, mode 2 -> g_resid [r][n]
// ---------------------------------------------------------------------------
__global__ void __launch_bounds__(256) gemm_kernel(
    const float* __restrict__ A, const float* __restrict__ Bw,
    const float* __restrict__ bias, int N, int mode)
{
    __shared__ float As[16][64];
    __shared__ float Bs[16][64];

    int tid  = threadIdx.x;
    int tx   = tid & 15;
    int ty   = tid >> 4;
    int row0 = blockIdx.x * 64;
    int col0 = blockIdx.y * 64;

    int lrow = tid >> 2;        // A: row within tile
    int lkq  = (tid & 3) * 4;   // A: k quad
    int lk   = tid >> 4;        // B: k row
    int lnq  = (tid & 15) * 4;  // B: col quad

    float2 acc[4][2];
#pragma unroll
    for (int i = 0; i < 4; i++) { acc[i][0] = make_float2(0.f, 0.f); acc[i][1] = make_float2(0.f, 0.f); }

    for (int k0 = 0; k0 < F_; k0 += 16) {
        float4 av = *(const float4*)(A + (size_t)(row0 + lrow) * F_ + k0 + lkq);
        As[lkq + 0][lrow] = av.x;
        As[lkq + 1][lrow] = av.y;
        As[lkq + 2][lrow] = av.z;
        As[lkq + 3][lrow] = av.w;
        *(float4*)(&Bs[lk][lnq]) = *(const float4*)(Bw + (size_t)(k0 + lk) * N + col0 + lnq);
        __syncthreads();

#pragma unroll
        for (int kk = 0; kk < 16; kk++) {
            float4 a4 = *(const float4*)(&As[kk][ty * 4]);
            float4 b4 = *(const float4*)(&Bs[kk][tx * 4]);
            float2 bp0 = make_float2(b4.x, b4.y);
            float2 bp1 = make_float2(b4.z, b4.w);
            float aa[4] = {a4.x, a4.y, a4.z, a4.w};
#pragma unroll
            for (int i = 0; i < 4; i++) {
                float2 ad = dup2(aa[i]);
                fma2(acc[i][0], ad, bp0);
                fma2(acc[i][1], ad, bp1);
            }
        }
        __syncthreads();
    }

    if (mode == 2) {
#pragma unroll
        for (int i = 0; i < 4; i++) {
            int r = row0 + ty * 4 + i;
            int c = col0 + tx * 4;
            g_resid[(size_t)r * P_ + c + 0] = acc[i][0].x;
            g_resid[(size_t)r * P_ + c + 1] = acc[i][0].y;
            g_resid[(size_t)r * P_ + c + 2] = acc[i][1].x;
            g_resid[(size_t)r * P_ + c + 3] = acc[i][1].y;
        }
    } else {
        float* outp = (mode == 1) ? g_xwb : g_xwf;
#pragma unroll
        for (int i = 0; i < 4; i++) {
            int r = row0 + ty * 4 + i;
            int b = r >> 10;       // r = b*1024 + t
            int t = r & 1023;
            int c = col0 + tx * 4;
            float v[4] = {acc[i][0].x, acc[i][0].y, acc[i][1].x, acc[i][1].y};
#pragma unroll
            for (int j = 0; j < 4; j++) {
                int g = c + j;
                outp[(size_t)t * GB_ + (size_t)g * B_ + b] = v[j] + bias[g];
            }
        }
    }
}

// ---------------------------------------------------------------------------
// Per-direction grid barrier (64 blocks each, all co-resident)
// ---------------------------------------------------------------------------
__device__ __forceinline__ void dir_barrier(int dir, unsigned target) {
    __syncthreads();
    if (threadIdx.x == 0) {
        __threadfence();
        unsigned prev = atomicAdd(&g_barc[dir], 1u);
        if (prev == 63u) {
            g_barc[dir] = 0u;
            __threadfence();
            atomicAdd(&g_barg[dir], 1u);
        } else {
            volatile unsigned* vg = &g_barg[dir];
            while (*vg < target) { __nanosleep(32); }
            __threadfence();
        }
    }
    __syncthreads();
}

// ---------------------------------------------------------------------------
// GRU recurrence. 128 blocks: 0..63 forward, 64..127 backward.
// Block owns 8 hidden units (U slice in 48KB static smem).
// 128 threads = 4 warps; warp owns 2 units; lane = batch pair (f32x2).
// ---------------------------------------------------------------------------
__global__ void __launch_bounds__(128) gru_kernel(
    const float* __restrict__ Ufm, const float* __restrict__ Ubm,
    const float* __restrict__ bfv, const float* __restrict__ bbv)
{
    __shared__ float Us[24 * 512];  // [c][k], c = gate*8 + local_unit; 49152 B

    int tid = threadIdx.x;
    int dir = blockIdx.x >> 6;
    int jb  = blockIdx.x & 63;

    const float* Um    = dir ? Ubm : Ufm;
    const float* brv   = (dir ? bbv : bfv) + G_;   // recurrent bias b[1]
    const float* xw    = dir ? g_xwb : g_xwf;
    float*       hout  = dir ? g_hb  : g_hf;
    float*       hbase = g_hbuf + (size_t)dir * 2 * HB_;

    // Load U slice: column c=(gate,uu) -> Um[:, gate*512 + jb*8 + uu]
    for (int idx = tid; idx < 24 * 512; idx += 128) {
        int c = idx >> 9;
        int k = idx & 511;
        int g  = c >> 3;
        int uu = c & 7;
        Us[c * 512 + k] = Um[(size_t)k * G_ + g * U_ + jb * 8 + uu];
    }

    int wid = tid >> 5;
    int bp  = tid & 31;
    int ul0 = wid * 2, ul1 = ul0 + 1;
    int ug0 = jb * 8 + ul0, ug1 = ug0 + 1;

    float brz0 = brv[ug0],          brz1 = brv[ug1];
    float brr0 = brv[U_ + ug0],     brr1 = brv[U_ + ug1];
    float brh0 = brv[2 * U_ + ug0], brh1 = brv[2 * U_ + ug1];

    const float4* UZ0 = (const float4*)(Us + (0 * 8 + ul0) * 512);
    const float4* UZ1 = (const float4*)(Us + (0 * 8 + ul1) * 512);
    const float4* UR0 = (const float4*)(Us + (1 * 8 + ul0) * 512);
    const float4* UR1 = (const float4*)(Us + (1 * 8 + ul1) * 512);
    const float4* UH0 = (const float4*)(Us + (2 * 8 + ul0) * 512);
    const float4* UH1 = (const float4*)(Us + (2 * 8 + ul1) * 512);

    __syncthreads();

    for (int s = 0; s < T_; s++) {
        int tt = dir ? (T_ - 1 - s) : s;

        // prefetch input projections (independent of h)
        const float2* XW2 = (const float2*)(xw + (size_t)tt * GB_);
        float2 xz0 = XW2[(size_t)(0 * U_ + ug0) * 32 + bp];
        float2 xz1 = XW2[(size_t)(0 * U_ + ug1) * 32 + bp];
        float2 xr0 = XW2[(size_t)(1 * U_ + ug0) * 32 + bp];
        float2 xr1 = XW2[(size_t)(1 * U_ + ug1) * 32 + bp];
        float2 xh0 = XW2[(size_t)(2 * U_ + ug0) * 32 + bp];
        float2 xh1 = XW2[(size_t)(2 * U_ + ug1) * 32 + bp];

        int par = s & 1;
        const float2* Hc = (const float2*)(hbase + (size_t)par * HB_);
        float2*       Hn = (float2*)(hbase + (size_t)(par ^ 1) * HB_);

        float2 az0 = {0.f, 0.f}, az1 = {0.f, 0.f};
        float2 ar0 = {0.f, 0.f}, ar1 = {0.f, 0.f};
        float2 ah0 = {0.f, 0.f}, ah1 = {0.f, 0.f};

#pragma unroll 2
        for (int k0 = 0; k0 < 512; k0 += 4) {
            float2 h0 = Hc[(size_t)(k0 + 0) * 32 + bp];
            float2 h1 = Hc[(size_t)(k0 + 1) * 32 + bp];
            float2 h2 = Hc[(size_t)(k0 + 2) * 32 + bp];
            float2 h3 = Hc[(size_t)(k0 + 3) * 32 + bp];
            float4 uz0 = UZ0[k0 >> 2], uz1 = UZ1[k0 >> 2];
            float4 ur0 = UR0[k0 >> 2], ur1 = UR1[k0 >> 2];
            float4 uh0 = UH0[k0 >> 2], uh1 = UH1[k0 >> 2];
            fma2(az0, dup2(uz0.x), h0); fma2(az0, dup2(uz0.y), h1);
            fma2(az0, dup2(uz0.z), h2); fma2(az0, dup2(uz0.w), h3);
            fma2(az1, dup2(uz1.x), h0); fma2(az1, dup2(uz1.y), h1);
            fma2(az1, dup2(uz1.z), h2); fma2(az1, dup2(uz1.w), h3);
            fma2(ar0, dup2(ur0.x), h0); fma2(ar0, dup2(ur0.y), h1);
            fma2(ar0, dup2(ur0.z), h2); fma2(ar0, dup2(ur0.w), h3);
            fma2(ar1, dup2(ur1.x), h0); fma2(ar1, dup2(ur1.y), h1);
            fma2(ar1, dup2(ur1.z), h2); fma2(ar1, dup2(ur1.w), h3);
            fma2(ah0, dup2(uh0.x), h0); fma2(ah0, dup2(uh0.y), h1);
            fma2(ah0, dup2(uh0.z), h2); fma2(ah0, dup2(uh0.w), h3);
            fma2(ah1, dup2(uh1.x), h0); fma2(ah1, dup2(uh1.y), h1);
            fma2(ah1, dup2(uh1.z), h2); fma2(ah1, dup2(uh1.w), h3);
        }

        float2 hold0 = Hc[(size_t)ug0 * 32 + bp];
        float2 hold1 = Hc[(size_t)ug1 * 32 + bp];

        // unit 0
        float z0x = 1.0f / (1.0f + expf(-(xz0.x + az0.x + brz0)));
        float z0y = 1.0f / (1.0f + expf(-(xz0.y + az0.y + brz0)));
        float r0x = 1.0f / (1.0f + expf(-(xr0.x + ar0.x + brr0)));
        float r0y = 1.0f / (1.0f + expf(-(xr0.y + ar0.y + brr0)));
        float hh0x = tanhf(xh0.x + r0x * (ah0.x + brh0));
        float hh0y = tanhf(xh0.y + r0y * (ah0.y + brh0));
        float hn0x = z0x * hold0.x + (1.0f - z0x) * hh0x;
        float hn0y = z0y * hold0.y + (1.0f - z0y) * hh0y;
        // unit 1
        float z1x = 1.0f / (1.0f + expf(-(xz1.x + az1.x + brz1)));
        float z1y = 1.0f / (1.0f + expf(-(xz1.y + az1.y + brz1)));
        float r1x = 1.0f / (1.0f + expf(-(xr1.x + ar1.x + brr1)));
        float r1y = 1.0f / (1.0f + expf(-(xr1.y + ar1.y + brr1)));
        float hh1x = tanhf(xh1.x + r1x * (ah1.x + brh1));
        float hh1y = tanhf(xh1.y + r1y * (ah1.y + brh1));
        float hn1x = z1x * hold1.x + (1.0f - z1x) * hh1x;
        float hn1y = z1y * hold1.y + (1.0f - z1y) * hh1y;

        Hn[(size_t)ug0 * 32 + bp] = make_float2(hn0x, hn0y);
        Hn[(size_t)ug1 * 32 + bp] = make_float2(hn1x, hn1y);

        int b0 = 2 * bp;
        hout[((size_t)b0 * T_ + tt) * U_ + ug0]       = hn0x;
        hout[((size_t)(b0 + 1) * T_ + tt) * U_ + ug0] = hn0y;
        hout[((size_t)b0 * T_ + tt) * U_ + ug1]       = hn1x;
        hout[((size_t)(b0 + 1) * T_ + tt) * U_ + ug1] = hn1y;

        dir_barrier(dir, (unsigned)(s + 1));
    }
}

// ---------------------------------------------------------------------------
// Epilogue: y = concat(hf,hb) + resid; LayerNorm over last dim (1024)
// ---------------------------------------------------------------------------
__global__ void __launch_bounds__(256) ln_kernel(
    const float* __restrict__ gamma, const float* __restrict__ beta,
    float* __restrict__ out)
{
    __shared__ float red[2][8];
    int row = blockIdx.x;       // b*T + t
    int tid = threadIdx.x;
    int c   = tid * 4;

    const float* hsrc = (tid < 128)
        ? (g_hf + (size_t)row * U_ + c)
        : (g_hb + (size_t)row * U_ + (c - U_));
    float4 h4 = *(const float4*)hsrc;
    float4 r4 = *(const float4*)(g_resid + (size_t)row * P_ + c);

    float y0 = h4.x + r4.x, y1 = h4.y + r4.y, y2 = h4.z + r4.z, y3 = h4.w + r4.w;
    float s  = y0 + y1 + y2 + y3;
    float s2 = y0 * y0 + y1 * y1 + y2 * y2 + y3 * y3;

#pragma unroll
    for (int off = 16; off > 0; off >>= 1) {
        s  += __shfl_xor_sync(0xFFFFFFFFu, s,  off);
        s2 += __shfl_xor_sync(0xFFFFFFFFu, s2, off);
    }
    int wid = tid >> 5, lane = tid & 31;
    if (lane == 0) { red[0][wid] = s; red[1][wid] = s2; }
    __syncthreads();
    s = 0.f; s2 = 0.f;
#pragma unroll
    for (int i = 0; i < 8; i++) { s += red[0][i]; s2 += red[1][i]; }

    float mu  = s * (1.0f / 1024.0f);
    float var = s2 * (1.0f / 1024.0f) - mu * mu;
    float inv = rsqrtf(var + EPS_);

    float4 g4 = *(const float4*)(gamma + c);
    float4 b4 = *(const float4*)(beta + c);
    float4 o;
    o.x = g4.x * (y0 - mu) * inv + b4.x;
    o.y = g4.y * (y1 - mu) * inv + b4.y;
    o.z = g4.z * (y2 - mu) * inv + b4.z;
    o.w = g4.w * (y3 - mu) * inv + b4.w;
    *(float4*)(out + (size_t)row * P_ + c) = o;
}

// ---------------------------------------------------------------------------
extern "C" void kernel_launch(void* const* d_in, const int* in_sizes, int n_in,
                              void* d_out, int out_size) {
    const float* x     = (const float*)d_in[0];
    const float* Wf    = (const float*)d_in[1];
    const float* Uf    = (const float*)d_in[2];
    const float* bf    = (const float*)d_in[3];
    const float* Wb    = (const float*)d_in[4];
    const float* Ub    = (const float*)d_in[5];
    const float* bb    = (const float*)d_in[6];
    const float* Wp    = (const float*)d_in[7];
    const float* gamma = (const float*)d_in[8];
    const float* beta  = (const float*)d_in[9];
    float* out = (float*)d_out;

    init_kernel<<<64, 256>>>();

    dim3 g1(1024, 24);  // 65536/64 x 1536/64
    dim3 g2(1024, 16);  // 65536/64 x 1024/64
    gemm_kernel<<<g1, 256>>>(x, Wf, bf, G_, 0);
    gemm_kernel<<<g1, 256>>>(x, Wb, bb, G_, 1);
    gemm_kernel<<<g2, 256>>>(x, Wp, nullptr, P_, 2);

    gru_kernel<<<128, 128>>>(Uf, Ub, bf, bb);

    ln_kernel<<<B_ * T_, 256>>>(gamma, beta, out);
}

// round 3
// speedup vs baseline: 1.2117x; 1.2117x over previous
#include <cuda_runtime.h>
#include <cstdint>

#define B_   64
#define T_   1024
#define F_   256
#define U_   512
#define G_   1536             // 3*U
#define P_   1024             // 2*U
#define GB_  (G_*B_)          // 98304
#define HB_  (U_*B_)          // 32768 floats per h ping-pong buffer
#define EPS_ 1e-3f

// ---------------------------------------------------------------------------
// Scratch: __device__ globals (allocation-free per harness rules)
// ---------------------------------------------------------------------------
__device__ float g_xwf[(size_t)T_ * G_ * B_];   // [T][G][B]  x@Wf + bi_f
__device__ float g_xwb[(size_t)T_ * G_ * B_];   // [T][G][B]  x@Wb + bi_b
__device__ float g_resid[(size_t)B_ * T_ * P_]; // [B*T][P]   x@Wp
__device__ float g_hf[(size_t)B_ * T_ * U_];    // [B][T][U]
__device__ float g_hb[(size_t)B_ * T_ * U_];    // [B][T][U]
__device__ float g_hbuf[2 * 2 * HB_];           // [dir][parity][U][B]
__device__ unsigned g_barc[2];                  // barrier arrive counters
__device__ unsigned g_barg[2];                  // barrier generations

// ---------------------------------------------------------------------------
// f32x2 packed FMA (Blackwell dual-fp32; only reachable via PTX)
// ---------------------------------------------------------------------------
__device__ __forceinline__ void fma2(float2& d, float2 a, float2 b) {
    unsigned long long& dd = reinterpret_cast<unsigned long long&>(d);
    unsigned long long& aa = reinterpret_cast<unsigned long long&>(a);
    unsigned long long& bb = reinterpret_cast<unsigned long long&>(b);
    asm("fma.rn.f32x2 %0, %1, %2, %0;" : "+l"(dd) : "l"(aa), "l"(bb));
}
__device__ __forceinline__ float2 dup2(float x) { return make_float2(x, x); }

// ---------------------------------------------------------------------------
// Init: zero h0 buffers + barrier state (graph replays reuse globals)
// ---------------------------------------------------------------------------
__global__ void init_kernel() {
    int idx = blockIdx.x * blockDim.x + threadIdx.x;
    int stride = gridDim.x * blockDim.x;
    for (int i = idx; i < 2 * 2 * HB_; i += stride) g_hbuf[i] = 0.0f;
    if (idx < 2) { g_barc[idx] = 0u; g_barg[idx] = 0u; }
}

// ---------------------------------------------------------------------------
// fp32 GEMM: A[BT,256] x Bw[256,N].  64x64 tile, BK=16, 256 threads.
//  mode 0 -> g_xwf [t][g][b] (+bias), mode 1 -> g_xwb, mode 2 -> g_resid [r][n]
// ---------------------------------------------------------------------------
__global__ void __launch_bounds__(256) gemm_kernel(
    const float* __restrict__ A, const float* __restrict__ Bw,
    const float* __restrict__ bias, int N, int mode)
{
    __shared__ float As[16][64];
    __shared__ float Bs[16][64];

    int tid  = threadIdx.x;
    int tx   = tid & 15;
    int ty   = tid >> 4;
    int row0 = blockIdx.x * 64;
    int col0 = blockIdx.y * 64;

    int lrow = tid >> 2;        // A: row within tile
    int lkq  = (tid & 3) * 4;   // A: k quad
    int lk   = tid >> 4;        // B: k row
    int lnq  = (tid & 15) * 4;  // B: col quad

    float2 acc[4][2];
#pragma unroll
    for (int i = 0; i < 4; i++) { acc[i][0] = make_float2(0.f, 0.f); acc[i][1] = make_float2(0.f, 0.f); }

    for (int k0 = 0; k0 < F_; k0 += 16) {
        float4 av = *(const float4*)(A + (size_t)(row0 + lrow) * F_ + k0 + lkq);
        As[lkq + 0][lrow] = av.x;
        As[lkq + 1][lrow] = av.y;
        As[lkq + 2][lrow] = av.z;
        As[lkq + 3][lrow] = av.w;
        *(float4*)(&Bs[lk][lnq]) = *(const float4*)(Bw + (size_t)(k0 + lk) * N + col0 + lnq);
        __syncthreads();

#pragma unroll
        for (int kk = 0; kk < 16; kk++) {
            float4 a4 = *(const float4*)(&As[kk][ty * 4]);
            float4 b4 = *(const float4*)(&Bs[kk][tx * 4]);
            float2 bp0 = make_float2(b4.x, b4.y);
            float2 bp1 = make_float2(b4.z, b4.w);
            float aa[4] = {a4.x, a4.y, a4.z, a4.w};
#pragma unroll
            for (int i = 0; i < 4; i++) {
                float2 ad = dup2(aa[i]);
                fma2(acc[i][0], ad, bp0);
                fma2(acc[i][1], ad, bp1);
            }
        }
        __syncthreads();
    }

    if (mode == 2) {
#pragma unroll
        for (int i = 0; i < 4; i++) {
            int r = row0 + ty * 4 + i;
            int c = col0 + tx * 4;
            g_resid[(size_t)r * P_ + c + 0] = acc[i][0].x;
            g_resid[(size_t)r * P_ + c + 1] = acc[i][0].y;
            g_resid[(size_t)r * P_ + c + 2] = acc[i][1].x;
            g_resid[(size_t)r * P_ + c + 3] = acc[i][1].y;
        }
    } else {
        float* outp = (mode == 1) ? g_xwb : g_xwf;
#pragma unroll
        for (int i = 0; i < 4; i++) {
            int r = row0 + ty * 4 + i;
            int b = r >> 10;       // r = b*1024 + t
            int t = r & 1023;
            int c = col0 + tx * 4;
            float v[4] = {acc[i][0].x, acc[i][0].y, acc[i][1].x, acc[i][1].y};
#pragma unroll
            for (int j = 0; j < 4; j++) {
                int g = c + j;
                outp[(size_t)t * GB_ + (size_t)g * B_ + b] = v[j] + bias[g];
            }
        }
    }
}

// ---------------------------------------------------------------------------
// Per-direction grid barrier (64 blocks each, all co-resident)
// ---------------------------------------------------------------------------
__device__ __forceinline__ void dir_barrier(int dir, unsigned target) {
    __syncthreads();
    if (threadIdx.x == 0) {
        __threadfence();
        unsigned prev = atomicAdd(&g_barc[dir], 1u);
        if (prev == 63u) {
            g_barc[dir] = 0u;
            __threadfence();
            atomicAdd(&g_barg[dir], 1u);
        } else {
            volatile unsigned* vg = &g_barg[dir];
            while (*vg < target) { __nanosleep(16); }
            __threadfence();
        }
    }
    __syncthreads();
}

// ---------------------------------------------------------------------------
// GRU recurrence v2. 128 blocks: 0..63 forward, 64..127 backward.
// Block owns 8 hidden units; 256 threads = 8 warps (2 per SMSP for hiding).
// Warp w: computes partial dots for unit pair up=w>>1 over k-half kh=w&1.
// Partials combined via smem; warps 0..3 finalize 2 units each.
// Dynamic smem: U slice 48KB + partials 12KB = 60KB.
// ---------------------------------------------------------------------------
__global__ void __launch_bounds__(256) gru_kernel(
    const float* __restrict__ Ufm, const float* __restrict__ Ubm,
    const float* __restrict__ bfv, const float* __restrict__ bbv)
{
    extern __shared__ float smem_[];
    float* Us = smem_;                                  // [24][512]
    float2 (*part)[6][32] = (float2 (*)[6][32])(smem_ + 24 * 512);  // [8][6][32]

    int tid = threadIdx.x;
    int dir = blockIdx.x >> 6;
    int jb  = blockIdx.x & 63;

    const float* Um    = dir ? Ubm : Ufm;
    const float* brv   = (dir ? bbv : bfv) + G_;   // recurrent bias b[1]
    const float* xw    = dir ? g_xwb : g_xwf;
    float*       hout  = dir ? g_hb  : g_hf;
    float*       hbase = g_hbuf + (size_t)dir * 2 * HB_;

    // Load U slice: column c=(gate,uu) -> Um[:, gate*512 + jb*8 + uu]
    for (int idx = tid; idx < 24 * 512; idx += 256) {
        int c = idx >> 9;
        int k = idx & 511;
        int g  = c >> 3;
        int uu = c & 7;
        Us[c * 512 + k] = Um[(size_t)k * G_ + g * U_ + jb * 8 + uu];
    }

    int w    = tid >> 5;
    int lane = tid & 31;
    int kh   = w & 1;          // k half: [kh*256, kh*256+256)
    int up   = w >> 1;         // unit pair 0..3
    int ul0  = up * 2, ul1 = ul0 + 1;

    // compute-role U pointers (float4 over k, offset by k-half)
    const float4* UZ0 = (const float4*)(Us + (0 * 8 + ul0) * 512 + kh * 256);
    const float4* UZ1 = (const float4*)(Us + (0 * 8 + ul1) * 512 + kh * 256);
    const float4* UR0 = (const float4*)(Us + (1 * 8 + ul0) * 512 + kh * 256);
    const float4* UR1 = (const float4*)(Us + (1 * 8 + ul1) * 512 + kh * 256);
    const float4* UH0 = (const float4*)(Us + (2 * 8 + ul0) * 512 + kh * 256);
    const float4* UH1 = (const float4*)(Us + (2 * 8 + ul1) * 512 + kh * 256);

    // finalize-role (warps 0..3): units 2w, 2w+1
    int fug0 = jb * 8 + 2 * w;
    int fug1 = fug0 + 1;
    float brz0 = 0.f, brz1 = 0.f, brr0 = 0.f, brr1 = 0.f, brh0 = 0.f, brh1 = 0.f;
    if (w < 4) {
        brz0 = brv[fug0];          brz1 = brv[fug1];
        brr0 = brv[U_ + fug0];     brr1 = brv[U_ + fug1];
        brh0 = brv[2 * U_ + fug0]; brh1 = brv[2 * U_ + fug1];
    }

    __syncthreads();

    for (int s = 0; s < T_; s++) {
        int tt = dir ? (T_ - 1 - s) : s;

        int par = s & 1;
        const float2* Hc = (const float2*)(hbase + (size_t)par * HB_);
        float2*       Hn = (float2*)(hbase + (size_t)(par ^ 1) * HB_);

        // finalize warps prefetch input projections + previous h (indep of dots)
        float2 xz0, xz1, xr0, xr1, xh0, xh1, hold0, hold1;
        if (w < 4) {
            const float2* XW2 = (const float2*)(xw + (size_t)tt * GB_);
            xz0 = XW2[(size_t)(0 * U_ + fug0) * 32 + lane];
            xz1 = XW2[(size_t)(0 * U_ + fug1) * 32 + lane];
            xr0 = XW2[(size_t)(1 * U_ + fug0) * 32 + lane];
            xr1 = XW2[(size_t)(1 * U_ + fug1) * 32 + lane];
            xh0 = XW2[(size_t)(2 * U_ + fug0) * 32 + lane];
            xh1 = XW2[(size_t)(2 * U_ + fug1) * 32 + lane];
            hold0 = Hc[(size_t)fug0 * 32 + lane];
            hold1 = Hc[(size_t)fug1 * 32 + lane];
        }

        // partial dot over this warp's k-half
        float2 az0 = {0.f, 0.f}, az1 = {0.f, 0.f};
        float2 ar0 = {0.f, 0.f}, ar1 = {0.f, 0.f};
        float2 ah0 = {0.f, 0.f}, ah1 = {0.f, 0.f};

        const float2* hp = Hc + (size_t)(kh * 256) * 32 + lane;

#pragma unroll 2
        for (int kq = 0; kq < 64; kq++) {
            int kb = kq * 4;
            float2 h0 = hp[(size_t)(kb + 0) * 32];
            float2 h1 = hp[(size_t)(kb + 1) * 32];
            float2 h2 = hp[(size_t)(kb + 2) * 32];
            float2 h3 = hp[(size_t)(kb + 3) * 32];
            float4 uz0 = UZ0[kq], uz1 = UZ1[kq];
            float4 ur0 = UR0[kq], ur1 = UR1[kq];
            float4 uh0 = UH0[kq], uh1 = UH1[kq];
            fma2(az0, dup2(uz0.x), h0); fma2(az0, dup2(uz0.y), h1);
            fma2(az0, dup2(uz0.z), h2); fma2(az0, dup2(uz0.w), h3);
            fma2(az1, dup2(uz1.x), h0); fma2(az1, dup2(uz1.y), h1);
            fma2(az1, dup2(uz1.z), h2); fma2(az1, dup2(uz1.w), h3);
            fma2(ar0, dup2(ur0.x), h0); fma2(ar0, dup2(ur0.y), h1);
            fma2(ar0, dup2(ur0.z), h2); fma2(ar0, dup2(ur0.w), h3);
            fma2(ar1, dup2(ur1.x), h0); fma2(ar1, dup2(ur1.y), h1);
            fma2(ar1, dup2(ur1.z), h2); fma2(ar1, dup2(ur1.w), h3);
            fma2(ah0, dup2(uh0.x), h0); fma2(ah0, dup2(uh0.y), h1);
            fma2(ah0, dup2(uh0.z), h2); fma2(ah0, dup2(uh0.w), h3);
            fma2(ah1, dup2(uh1.x), h0); fma2(ah1, dup2(uh1.y), h1);
            fma2(ah1, dup2(uh1.z), h2); fma2(ah1, dup2(uh1.w), h3);
        }

        part[w][0][lane] = az0; part[w][1][lane] = az1;
        part[w][2][lane] = ar0; part[w][3][lane] = ar1;
        part[w][4][lane] = ah0; part[w][5][lane] = ah1;
        __syncthreads();

        if (w < 4) {
            // combine k-halves from partner warps 2w and 2w+1
            float2 paz0 = part[2 * w][0][lane], qaz0 = part[2 * w + 1][0][lane];
            float2 paz1 = part[2 * w][1][lane], qaz1 = part[2 * w + 1][1][lane];
            float2 par0 = part[2 * w][2][lane], qar0 = part[2 * w + 1][2][lane];
            float2 par1 = part[2 * w][3][lane], qar1 = part[2 * w + 1][3][lane];
            float2 pah0 = part[2 * w][4][lane], qah0 = part[2 * w + 1][4][lane];
            float2 pah1 = part[2 * w][5][lane], qah1 = part[2 * w + 1][5][lane];
            float azx0 = paz0.x + qaz0.x, azy0 = paz0.y + qaz0.y;
            float azx1 = paz1.x + qaz1.x, azy1 = paz1.y + qaz1.y;
            float arx0 = par0.x + qar0.x, ary0 = par0.y + qar0.y;
            float arx1 = par1.x + qar1.x, ary1 = par1.y + qar1.y;
            float ahx0 = pah0.x + qah0.x, ahy0 = pah0.y + qah0.y;
            float ahx1 = pah1.x + qah1.x, ahy1 = pah1.y + qah1.y;

            // unit 0 of pair
            float z0x = 1.0f / (1.0f + expf(-(xz0.x + azx0 + brz0)));
            float z0y = 1.0f / (1.0f + expf(-(xz0.y + azy0 + brz0)));
            float r0x = 1.0f / (1.0f + expf(-(xr0.x + arx0 + brr0)));
            float r0y = 1.0f / (1.0f + expf(-(xr0.y + ary0 + brr0)));
            float hh0x = tanhf(xh0.x + r0x * (ahx0 + brh0));
            float hh0y = tanhf(xh0.y + r0y * (ahy0 + brh0));
            float hn0x = z0x * hold0.x + (1.0f - z0x) * hh0x;
            float hn0y = z0y * hold0.y + (1.0f - z0y) * hh0y;
            // unit 1 of pair
            float z1x = 1.0f / (1.0f + expf(-(xz1.x + azx1 + brz1)));
            float z1y = 1.0f / (1.0f + expf(-(xz1.y + azy1 + brz1)));
            float r1x = 1.0f / (1.0f + expf(-(xr1.x + arx1 + brr1)));
            float r1y = 1.0f / (1.0f + expf(-(xr1.y + ary1 + brr1)));
            float hh1x = tanhf(xh1.x + r1x * (ahx1 + brh1));
            float hh1y = tanhf(xh1.y + r1y * (ahy1 + brh1));
            float hn1x = z1x * hold1.x + (1.0f - z1x) * hh1x;
            float hn1y = z1y * hold1.y + (1.0f - z1y) * hh1y;

            Hn[(size_t)fug0 * 32 + lane] = make_float2(hn0x, hn0y);
            Hn[(size_t)fug1 * 32 + lane] = make_float2(hn1x, hn1y);

            int b0 = 2 * lane;
            hout[((size_t)b0 * T_ + tt) * U_ + fug0]       = hn0x;
            hout[((size_t)(b0 + 1) * T_ + tt) * U_ + fug0] = hn0y;
            hout[((size_t)b0 * T_ + tt) * U_ + fug1]       = hn1x;
            hout[((size_t)(b0 + 1) * T_ + tt) * U_ + fug1] = hn1y;
        }

        dir_barrier(dir, (unsigned)(s + 1));
    }
}

// ---------------------------------------------------------------------------
// Epilogue: y = concat(hf,hb) + resid; LayerNorm over last dim (1024)
// ---------------------------------------------------------------------------
__global__ void __launch_bounds__(256) ln_kernel(
    const float* __restrict__ gamma, const float* __restrict__ beta,
    float* __restrict__ out)
{
    __shared__ float red[2][8];
    int row = blockIdx.x;       // b*T + t
    int tid = threadIdx.x;
    int c   = tid * 4;

    const float* hsrc = (tid < 128)
        ? (g_hf + (size_t)row * U_ + c)
        : (g_hb + (size_t)row * U_ + (c - U_));
    float4 h4 = *(const float4*)hsrc;
    float4 r4 = *(const float4*)(g_resid + (size_t)row * P_ + c);

    float y0 = h4.x + r4.x, y1 = h4.y + r4.y, y2 = h4.z + r4.z, y3 = h4.w + r4.w;
    float s  = y0 + y1 + y2 + y3;
    float s2 = y0 * y0 + y1 * y1 + y2 * y2 + y3 * y3;

#pragma unroll
    for (int off = 16; off > 0; off >>= 1) {
        s  += __shfl_xor_sync(0xFFFFFFFFu, s,  off);
        s2 += __shfl_xor_sync(0xFFFFFFFFu, s2, off);
    }
    int wid = tid >> 5, lane = tid & 31;
    if (lane == 0) { red[0][wid] = s; red[1][wid] = s2; }
    __syncthreads();
    s = 0.f; s2 = 0.f;
#pragma unroll
    for (int i = 0; i < 8; i++) { s += red[0][i]; s2 += red[1][i]; }

    float mu  = s * (1.0f / 1024.0f);
    float var = s2 * (1.0f / 1024.0f) - mu * mu;
    float inv = rsqrtf(var + EPS_);

    float4 g4 = *(const float4*)(gamma + c);
    float4 b4 = *(const float4*)(beta + c);
    float4 o;
    o.x = g4.x * (y0 - mu) * inv + b4.x;
    o.y = g4.y * (y1 - mu) * inv + b4.y;
    o.z = g4.z * (y2 - mu) * inv + b4.z;
    o.w = g4.w * (y3 - mu) * inv + b4.w;
    *(float4*)(out + (size_t)row * P_ + c) = o;
}

// ---------------------------------------------------------------------------
extern "C" void kernel_launch(void* const* d_in, const int* in_sizes, int n_in,
                              void* d_out, int out_size) {
    const float* x     = (const float*)d_in[0];
    const float* Wf    = (const float*)d_in[1];
    const float* Uf    = (const float*)d_in[2];
    const float* bf    = (const float*)d_in[3];
    const float* Wb    = (const float*)d_in[4];
    const float* Ub    = (const float*)d_in[5];
    const float* bb    = (const float*)d_in[6];
    const float* Wp    = (const float*)d_in[7];
    const float* gamma = (const float*)d_in[8];
    const float* beta  = (const float*)d_in[9];
    float* out = (float*)d_out;

    const int gru_smem = 24 * 512 * 4 + 8 * 6 * 32 * 8;  // 61440 B
    cudaFuncSetAttribute(gru_kernel, cudaFuncAttributeMaxDynamicSharedMemorySize, gru_smem);

    init_kernel<<<64, 256>>>();

    dim3 g1(1024, 24);  // 65536/64 x 1536/64
    dim3 g2(1024, 16);  // 65536/64 x 1024/64
    gemm_kernel<<<g1, 256>>>(x, Wf, bf, G_, 0);
    gemm_kernel<<<g1, 256>>>(x, Wb, bb, G_, 1);
    gemm_kernel<<<g2, 256>>>(x, Wp, nullptr, P_, 2);

    gru_kernel<<<128, 256, gru_smem>>>(Uf, Ub, bf, bb);

    ln_kernel<<<B_ * T_, 256>>>(gamma, beta, out);
}